// round 1
// baseline (speedup 1.0000x reference)
#include <cuda_runtime.h>
#include <math.h>

#define W_IMG 4096
#define PI_C 3.141592657f

// Compute X, Y, Z, D for pixel (r,c); out-of-bounds -> all zeros (matches
// _shift zero padding applied to the X/Y/Z/D arrays).
__device__ __forceinline__ void pix_xyzd(const float* __restrict__ depth,
                                         int r, int c, int h, int w,
                                         float inv_fx, float cx, float cy,
                                         float& X, float& Y, float& Z, float& D) {
    if (r < 0 || r >= h || c < 0 || c >= w) {
        X = 0.f; Y = 0.f; Z = 0.f; D = 0.f;
        return;
    }
    float d = depth[(long)r * w + c];
    Z = d;
    Y = Z * ((float)r - cy) * inv_fx;     // reference uses fx for Y too
    X = Z * ((float)c - cx) * inv_fx;
    if (Y <= 0.f) { Z = 0.f; Y = 0.f; }   // X intentionally NOT zeroed (matches reference)
    if (isnan(Z)) Z = 0.f;
    D = 1.0f / Z;                          // inf where Z == 0, as in reference
}

__global__ void nim_kernel(const float* __restrict__ depth,
                           const float* __restrict__ cam,
                           const int*   __restrict__ sf_ptr,
                           float* __restrict__ out,
                           int h, int w) {
    int c = blockIdx.x * blockDim.x + threadIdx.x;
    int r = blockIdx.y * blockDim.y + threadIdx.y;
    if (r >= h || c >= w) return;

    float fx = cam[0];
    float fy = cam[4];
    float cx = cam[2];
    float cy = cam[5];
    float inv_fx = 1.0f / fx;
    int sign_filter = sf_ptr[0];

    // Center + 4 neighbors in diffs order: (-1,0), (0,-1), (0,1), (1,0)
    float Xc, Yc, Zc, Dc;
    pix_xyzd(depth, r, c, h, w, inv_fx, cx, cy, Xc, Yc, Zc, Dc);

    const int dy[4] = {-1, 0, 0, 1};
    const int dx[4] = { 0,-1, 1, 0};
    float Xn[4], Yn[4], Zn[4], Dn[4];
#pragma unroll
    for (int i = 0; i < 4; i++) {
        pix_xyzd(depth, r + dy[i], c + dx[i], h, w, inv_fx, cx, cy,
                 Xn[i], Yn[i], Zn[i], Dn[i]);
    }

    // Gu = D[r, c+1] - D[r, c-1];  Gv = D[r+1, c] - D[r-1, c]
    float Gu = Dn[2] - Dn[1];
    float Gv = Dn[3] - Dn[0];
    float nx_t = Gu * fx;
    float ny_t = Gv * fy;

    float phi = atanf(ny_t / nx_t) + PI_C;
    float a, b;
    sincosf(phi, &b, &a);   // a = cos(phi), b = sin(phi)

    float nxv[4], nyv[4], nzv[4];
    float nt2 = nx_t * nx_t + ny_t * ny_t;
#pragma unroll
    for (int i = 0; i < 4; i++) {
        float Xd = Xc - Xn[i];
        float Yd = Yc - Yn[i];
        float Zd = Zc - Zn[i];
        float nz_i = -(nx_t * Xd + ny_t * Yd) / Zd;
        float norm = sqrtf(nt2 + nz_i * nz_i);
        float vx = nx_t / norm;
        float vy = ny_t / norm;
        float vz = nz_i / norm;
        nxv[i] = isnan(vx) ? 0.f : vx;
        nyv[i] = isnan(vy) ? 0.f : vy;
        nzv[i] = isnan(vz) ? 0.f : vz;
    }

    if (sign_filter) {
        int n_pos = 0, n_neg = 0;
#pragma unroll
        for (int i = 0; i < 4; i++) {
            n_pos += (nzv[i] > 0.f) ? 1 : 0;
            n_neg += (nzv[i] < 0.f) ? 1 : 0;
        }
#pragma unroll
        for (int i = 0; i < 4; i++) {
            bool keep = (n_pos >= n_neg) ? (nzv[i] > 0.f) : (nzv[i] < 0.f);
            float fm = keep ? 1.f : 0.f;
            nxv[i] *= fm;
            nyv[i] *= fm;
            nzv[i] *= fm;
        }
    }

    float snx = nxv[0] + nxv[1] + nxv[2] + nxv[3];
    float sny = nyv[0] + nyv[1] + nyv[2] + nyv[3];
    float snz = nzv[0] + nzv[1] + nzv[2] + nzv[3];

    float theta = atanf((snx * a + sny * b) / snz);
    float st, ct;
    sincosf(theta, &st, &ct);
    float nx = st * a;
    float ny = st * b;
    float nz = ct;
    if (isnan(nz)) { nx = 0.f; ny = 0.f; nz = -1.f; }

    float s = (ny > 0.f) ? -1.f : 1.f;

    long hw = (long)h * w;
    long idx = (long)r * w + c;
    out[idx]          = nx * s;
    out[hw + idx]     = ny * s;
    out[2 * hw + idx] = nz * s;
}

extern "C" void kernel_launch(void* const* d_in, const int* in_sizes, int n_in,
                              void* d_out, int out_size) {
    const float* depth = (const float*)d_in[0];
    const float* cam   = (const float*)d_in[1];
    const int*   sf    = (const int*)d_in[2];
    float* out = (float*)d_out;

    int w = W_IMG;
    int h = in_sizes[0] / w;

    dim3 block(32, 8);
    dim3 grid((w + block.x - 1) / block.x, (h + block.y - 1) / block.y);
    nim_kernel<<<grid, block>>>(depth, cam, sf, out, h, w);
}

// round 2
// speedup vs baseline: 1.7053x; 1.7053x over previous
#include <cuda_runtime.h>
#include <math.h>

#define W_IMG 4096
// float(pi) - pi  (so cos(pi_f) == -1.0f exactly, sin(pi_f) == -DPI)
#define DPI 8.742278e-8f

__device__ __forceinline__ float rcpa(float x) {
    float y; asm("rcp.approx.f32 %0, %1;" : "=f"(y) : "f"(x)); return y;
}
__device__ __forceinline__ float rsqa(float x) {
    float y; asm("rsqrt.approx.f32 %0, %1;" : "=f"(y) : "f"(x)); return y;
}

// X, Y, Z for pixel (r,c); OOB -> zeros (matches _shift zero padding of the
// X/Y/Z arrays in the reference).
__device__ __forceinline__ void pix_xyz(const float* __restrict__ depth,
                                        int r, int c, int h, int w,
                                        float inv_fx, float cx, float cy,
                                        float& X, float& Y, float& Z, bool& inb) {
    inb = (r >= 0) & (r < h) & (c >= 0) & (c < w);
    if (!inb) { X = 0.f; Y = 0.f; Z = 0.f; return; }
    float z = depth[r * w + c];
    Z = z;
    Y = z * ((float)r - cy) * inv_fx;   // reference uses fx for Y too
    X = z * ((float)c - cx) * inv_fx;
    if (Y <= 0.f) { Z = 0.f; Y = 0.f; } // X intentionally NOT zeroed (matches ref)
    if (isnan(Z)) Z = 0.f;
}

// cos/sin of (atan(num/den) + pi_f): robust to inf/NaN/signed-zero exactly as
// IEEE atanf+sincosf would propagate them.
__device__ __forceinline__ void cs_atan_pi(float num, float den, float& a, float& b) {
    float an = fabsf(num), ad = fabsf(den);
    if (an <= ad) {
        float t  = num * rcpa(den);            // |t| <= 1, or NaN
        float rr = rsqa(fmaf(t, t, 1.f));      // cos(atan t)
        float sa = t * rr;                     // sin(atan t)
        a = fmaf(sa, DPI, -rr);                // cos(atan t + pi_f)
        b = -fmaf(rr, DPI, sa);                // sin(atan t + pi_f)
    } else {
        float s  = den * rcpa(num);            // |s| < 1, or NaN
        float sg = copysignf(1.f, num) * copysignf(1.f, den);
        float rr = rsqa(fmaf(s, s, 1.f));
        float ca = fabsf(s) * rr;              // cos(atan t)
        float sa = sg * rr;                    // sin(atan t)
        a = fmaf(sa, DPI, -ca);
        b = -fmaf(ca, DPI, sa);
    }
}

// sin/cos of atan(num/den), same robustness.
__device__ __forceinline__ void sc_atan(float num, float den, float& st, float& ct) {
    float an = fabsf(num), ad = fabsf(den);
    if (an <= ad) {
        float q  = num * rcpa(den);
        float rr = rsqa(fmaf(q, q, 1.f));
        st = q * rr;
        ct = rr;
    } else {
        float p  = den * rcpa(num);
        float sg = copysignf(1.f, num) * copysignf(1.f, den);
        float rr = rsqa(fmaf(p, p, 1.f));
        st = sg * rr;
        ct = fabsf(p) * rr;
    }
}

__global__ void nim_kernel(const float* __restrict__ depth,
                           const float* __restrict__ cam,
                           const int*   __restrict__ sf_ptr,
                           float* __restrict__ out,
                           int h, int w) {
    int c = blockIdx.x * blockDim.x + threadIdx.x;
    int r = blockIdx.y * blockDim.y + threadIdx.y;
    if (r >= h || c >= w) return;

    float fx = cam[0];
    float fy = cam[4];
    float cx = cam[2];
    float cy = cam[5];
    float inv_fx = 1.0f / fx;
    int sign_filter = sf_ptr[0];

    // Center + 4 neighbors, diffs order: (-1,0), (0,-1), (0,1), (1,0)
    float Xc, Yc, Zc; bool inc;
    pix_xyz(depth, r, c, h, w, inv_fx, cx, cy, Xc, Yc, Zc, inc);

    const int dy[4] = {-1, 0, 0, 1};
    const int dx[4] = { 0,-1, 1, 0};
    float Xn[4], Yn[4], Zn[4], Dn[4];
#pragma unroll
    for (int i = 0; i < 4; i++) {
        bool inb;
        pix_xyz(depth, r + dy[i], c + dx[i], h, w, inv_fx, cx, cy,
                Xn[i], Yn[i], Zn[i], inb);
        // D is zero-padded at the border (shift applied to D), inf where Z==0
        Dn[i] = inb ? __frcp_rn(Zn[i]) : 0.f;
    }

    float Gu = Dn[2] - Dn[1];
    float Gv = Dn[3] - Dn[0];
    float nx_t = Gu * fx;
    float ny_t = Gv * fy;

    float a, b;
    cs_atan_pi(ny_t, nx_t, a, b);   // a = cos(phi), b = sin(phi)

    float nt2 = fmaf(nx_t, nx_t, ny_t * ny_t);
    float nxv[4], nyv[4], nzv[4];
#pragma unroll
    for (int i = 0; i < 4; i++) {
        float Xd = Xc - Xn[i];
        float Yd = Yc - Yn[i];
        float Zd = Zc - Zn[i];
        float nz_i = -fmaf(nx_t, Xd, ny_t * Yd) * rcpa(Zd);
        float rn = rsqa(fmaf(nz_i, nz_i, nt2));
        float vx = nx_t * rn;
        float vy = ny_t * rn;
        float vz = nz_i * rn;
        nxv[i] = (vx != vx) ? 0.f : vx;
        nyv[i] = (vy != vy) ? 0.f : vy;
        nzv[i] = (vz != vz) ? 0.f : vz;
    }

    if (sign_filter) {
        int n_pos = 0, n_neg = 0;
#pragma unroll
        for (int i = 0; i < 4; i++) {
            n_pos += (nzv[i] > 0.f) ? 1 : 0;
            n_neg += (nzv[i] < 0.f) ? 1 : 0;
        }
        bool pos_side = (n_pos >= n_neg);
#pragma unroll
        for (int i = 0; i < 4; i++) {
            bool keep = pos_side ? (nzv[i] > 0.f) : (nzv[i] < 0.f);
            float fm = keep ? 1.f : 0.f;
            nxv[i] *= fm;
            nyv[i] *= fm;
            nzv[i] *= fm;
        }
    }

    float snx = (nxv[0] + nxv[1]) + (nxv[2] + nxv[3]);
    float sny = (nyv[0] + nyv[1]) + (nyv[2] + nyv[3]);
    float snz = (nzv[0] + nzv[1]) + (nzv[2] + nzv[3]);

    float num = fmaf(snx, a, sny * b);
    float st, ct;
    sc_atan(num, snz, st, ct);      // st = sin(theta), ct = cos(theta)

    float nx = st * a;
    float ny = st * b;
    float nz = ct;
    if (nz != nz) { nx = 0.f; ny = 0.f; nz = -1.f; }

    float s = (ny > 0.f) ? -1.f : 1.f;

    int hw = h * w;
    int idx = r * w + c;
    out[idx]           = nx * s;
    out[idx + hw]      = ny * s;
    out[idx + 2 * hw]  = nz * s;
}

extern "C" void kernel_launch(void* const* d_in, const int* in_sizes, int n_in,
                              void* d_out, int out_size) {
    const float* depth = (const float*)d_in[0];
    const float* cam   = (const float*)d_in[1];
    const int*   sf    = (const int*)d_in[2];
    float* out = (float*)d_out;

    int w = W_IMG;
    int h = in_sizes[0] / w;

    dim3 block(32, 8);
    dim3 grid((w + block.x - 1) / block.x, (h + block.y - 1) / block.y);
    nim_kernel<<<grid, block>>>(depth, cam, sf, out, h, w);
}

// round 3
// speedup vs baseline: 3.7291x; 2.1868x over previous
#include <cuda_runtime.h>
#include <math.h>

#define W_IMG 4096
// float(pi) - pi  (cos(pi_f) == -1 exactly, sin(pi_f) == -DPI)
#define DPI 8.742278e-8f

__device__ __forceinline__ float rcpa(float x){ float y; asm("rcp.approx.f32 %0, %1;" : "=f"(y) : "f"(x)); return y; }
__device__ __forceinline__ float rsqa(float x){ float y; asm("rsqrt.approx.f32 %0, %1;" : "=f"(y) : "f"(x)); return y; }

// Branchless sin/cos of atan(num/den). Handles inf/NaN/signed-zero exactly as
// IEEE atanf+sincosf would: picks the <=1-magnitude ratio via selects, single
// rcp + rsqrt.
__device__ __forceinline__ void cs_atan_core(float num, float den, float& sa, float& ca) {
    float an = fabsf(num), ad = fabsf(den);
    bool sw = an > ad;
    float top = sw ? den : num;
    float bot = sw ? num : den;
    float q  = top * rcpa(bot);                 // |q| <= 1, or NaN
    float rr = rsqa(fmaf(q, q, 1.f));
    float sg = copysignf(1.f, num) * copysignf(1.f, den);
    ca = sw ? fabsf(q) * rr : rr;
    sa = sw ? sg * rr : q * rr;
}

// Final stage: from nx_t, ny_t and the 4 neighbor diffs to the output normal.
__device__ __forceinline__ void finish_pixel(
    float nx_t, float ny_t,
    const float* Xd, const float* Yd, const float* Zd,
    int sf, float& onx, float& ony, float& onz)
{
    float sa, ca; cs_atan_core(ny_t, nx_t, sa, ca);
    float a = fmaf(sa, DPI, -ca);       // cos(atan + pi_f)
    float b = -fmaf(ca, DPI, sa);       // sin(atan + pi_f)
    float nt2 = fmaf(nx_t, nx_t, ny_t * ny_t);

    float nxv[4], nyv[4], nzv[4];
#pragma unroll
    for (int i = 0; i < 4; i++) {
        float nz_i = -fmaf(nx_t, Xd[i], ny_t * Yd[i]) * rcpa(Zd[i]);
        float rn = rsqa(fmaf(nz_i, nz_i, nt2));
        float vx = nx_t * rn, vy = ny_t * rn, vz = nz_i * rn;
        nxv[i] = (vx != vx) ? 0.f : vx;
        nyv[i] = (vy != vy) ? 0.f : vy;
        nzv[i] = (vz != vz) ? 0.f : vz;
    }
    if (sf) {
        int n_pos = 0, n_neg = 0;
#pragma unroll
        for (int i = 0; i < 4; i++) { n_pos += nzv[i] > 0.f; n_neg += nzv[i] < 0.f; }
        bool ps = (n_pos >= n_neg);
#pragma unroll
        for (int i = 0; i < 4; i++) {
            float fm = (ps ? (nzv[i] > 0.f) : (nzv[i] < 0.f)) ? 1.f : 0.f;
            nxv[i] *= fm; nyv[i] *= fm; nzv[i] *= fm;
        }
    }
    float snx = (nxv[0] + nxv[1]) + (nxv[2] + nxv[3]);
    float sny = (nyv[0] + nyv[1]) + (nyv[2] + nyv[3]);
    float snz = (nzv[0] + nzv[1]) + (nzv[2] + nzv[3]);

    float num = fmaf(snx, a, sny * b);
    float st, ct; cs_atan_core(num, snz, st, ct);
    float nx = st * a, ny = st * b, nz = ct;
    if (nz != nz) { nx = 0.f; ny = 0.f; nz = -1.f; }
    float s = (ny > 0.f) ? -1.f : 1.f;
    onx = nx * s; ony = ny * s; onz = nz * s;
}

// Fully general per-pixel path (borders, horizon band, pathological depth).
__device__ __noinline__ void generic_pixel(const float* __restrict__ depth,
    int r, int c, int h, int w, float fx, float fy, float ifx,
    float cx, float cy, int sf, float& onx, float& ony, float& onz)
{
    // order: center, then (-1,0), (0,-1), (0,1), (1,0)
    const int dy[5] = {0, -1, 0, 0, 1};
    const int dx[5] = {0,  0,-1, 1, 0};
    float Xs[5], Ys[5], Zs[5], Ds[5];
#pragma unroll
    for (int i = 0; i < 5; i++) {
        int rr_ = r + dy[i], cc = c + dx[i];
        bool inb = (rr_ >= 0) & (rr_ < h) & (cc >= 0) & (cc < w);
        float X = 0.f, Y = 0.f, Z = 0.f, D = 0.f;
        if (inb) {
            float z = depth[rr_ * w + cc];
            Z = z;
            Y = z * ((float)rr_ - cy) * ifx;   // reference uses fx for Y too
            X = z * ((float)cc - cx) * ifx;
            if (Y <= 0.f) { Z = 0.f; Y = 0.f; } // X intentionally NOT zeroed
            if (Z != Z) Z = 0.f;                // NaN -> 0
            D = rcpa(Z);                         // inf where Z == 0
        }
        Xs[i] = X; Ys[i] = Y; Zs[i] = Z; Ds[i] = D;
    }
    float nx_t = (Ds[3] - Ds[2]) * fx;
    float ny_t = (Ds[4] - Ds[1]) * fy;
    float Xd[4], Yd[4], Zd[4];
#pragma unroll
    for (int i = 0; i < 4; i++) {
        Xd[i] = Xs[0] - Xs[i + 1];
        Yd[i] = Ys[0] - Ys[i + 1];
        Zd[i] = Zs[0] - Zs[i + 1];
    }
    finish_pixel(nx_t, ny_t, Xd, Yd, Zd, sf, onx, ony, onz);
}

__global__ __launch_bounds__(128)
void nim_kernel(const float* __restrict__ depth,
                const float* __restrict__ cam,
                const int*   __restrict__ sf_ptr,
                float* __restrict__ out,
                int h, int w)
{
    int r  = blockIdx.y * 4 + threadIdx.y;
    int c0 = (blockIdx.x * 32 + threadIdx.x) * 4;
    if (r >= h || c0 + 3 >= w) return;

    float fx = cam[0], fy = cam[4], cx = cam[2], cy = cam[5];
    float ifx = 1.0f / fx;
    int sf = sf_ptr[0];
    int hw = h * w;
    int base = r * w + c0;

    bool interior = (r >= 1) & (r < h - 1) & (c0 >= 4) & (c0 <= w - 8);

    if (interior) {
        float4 zu4 = *(const float4*)(depth + base - w);
        float4 zd4 = *(const float4*)(depth + base + w);
        float4 zm4 = *(const float4*)(depth + base);
        float  zml = depth[base - 1];
        float  zmr = depth[base + 4];

        float zu[4] = {zu4.x, zu4.y, zu4.z, zu4.w};
        float zd[4] = {zd4.x, zd4.y, zd4.z, zd4.w};
        float zm[6] = {zml, zm4.x, zm4.y, zm4.z, zm4.w, zmr};

        float fv0 = ((float)r       - cy) * ifx;
        float fvm = ((float)(r - 1) - cy) * ifx;
        float fvp = ((float)(r + 1) - cy) * ifx;

        // NaN-safe strict-positivity of the full 14-depth neighborhood
        bool allpos = (zu[0] > 0.f) & (zu[1] > 0.f) & (zu[2] > 0.f) & (zu[3] > 0.f)
                    & (zd[0] > 0.f) & (zd[1] > 0.f) & (zd[2] > 0.f) & (zd[3] > 0.f)
                    & (zm[0] > 0.f) & (zm[1] > 0.f) & (zm[2] > 0.f)
                    & (zm[3] > 0.f) & (zm[4] > 0.f) & (zm[5] > 0.f);

        if (allpos && fvp <= 0.f) {
            // Whole 3x6 neighborhood has Y<=0 -> Z=0 -> D=inf everywhere ->
            // NaN cascade -> reference emits exactly (0, 0, -1).
            float4 zro = make_float4(0.f, 0.f, 0.f, 0.f);
            float4 neg = make_float4(-1.f, -1.f, -1.f, -1.f);
            *(float4*)(out + base)          = zro;
            *(float4*)(out + base + hw)     = zro;
            *(float4*)(out + base + 2 * hw) = neg;
            return;
        }

        if (allpos && fvm > 0.f) {
            // Fully unmasked rows: Z=z, Y=z*fv, X=z*fu, D=1/z.
            float Dm[6], Xm[6], Du[4], Dd[4];
#pragma unroll
            for (int j = 0; j < 6; j++) {
                float fu = ((float)(c0 - 1 + j) - cx) * ifx;
                Xm[j] = zm[j] * fu;
                Dm[j] = rcpa(zm[j]);
            }
#pragma unroll
            for (int p = 0; p < 4; p++) { Du[p] = rcpa(zu[p]); Dd[p] = rcpa(zd[p]); }

            float4 ox, oy, oz;
            float* oxp = &ox.x; float* oyp = &oy.x; float* ozp = &oz.x;
#pragma unroll
            for (int p = 0; p < 4; p++) {
                float zc  = zm[p + 1];
                float fuc = ((float)(c0 + p) - cx) * ifx;

                float nx_t = (Dm[p + 2] - Dm[p]) * fx;
                float ny_t = (Dd[p] - Du[p]) * fy;

                // neighbor order: 0:up(-1,0) 1:left(0,-1) 2:right(0,1) 3:down(1,0)
                float Xd[4], Yd[4], Zd[4];
                Zd[0] = zc - zu[p];
                Xd[0] = Zd[0] * fuc;
                Yd[0] = fmaf(zc, fv0, -(zu[p] * fvm));
                Zd[1] = zc - zm[p];
                Xd[1] = Xm[p + 1] - Xm[p];
                Yd[1] = Zd[1] * fv0;
                Zd[2] = zc - zm[p + 2];
                Xd[2] = Xm[p + 1] - Xm[p + 2];
                Yd[2] = Zd[2] * fv0;
                Zd[3] = zc - zd[p];
                Xd[3] = Zd[3] * fuc;
                Yd[3] = fmaf(zc, fv0, -(zd[p] * fvp));

                finish_pixel(nx_t, ny_t, Xd, Yd, Zd, sf, oxp[p], oyp[p], ozp[p]);
            }
            *(float4*)(out + base)          = ox;
            *(float4*)(out + base + hw)     = oy;
            *(float4*)(out + base + 2 * hw) = oz;
            return;
        }
    }

    // Generic path: borders, horizon band, or unusual depth values.
    for (int p = 0; p < 4; p++) {
        float onx, ony, onz;
        generic_pixel(depth, r, c0 + p, h, w, fx, fy, ifx, cx, cy, sf, onx, ony, onz);
        out[base + p]          = onx;
        out[base + p + hw]     = ony;
        out[base + p + 2 * hw] = onz;
    }
}

extern "C" void kernel_launch(void* const* d_in, const int* in_sizes, int n_in,
                              void* d_out, int out_size) {
    const float* depth = (const float*)d_in[0];
    const float* cam   = (const float*)d_in[1];
    const int*   sf    = (const int*)d_in[2];
    float* out = (float*)d_out;

    int w = W_IMG;
    int h = in_sizes[0] / w;

    dim3 block(32, 4);
    dim3 grid((w + 127) / 128, (h + 3) / 4);
    nim_kernel<<<grid, block>>>(depth, cam, sf, out, h, w);
}

// round 4
// speedup vs baseline: 4.2936x; 1.1514x over previous
#include <cuda_runtime.h>
#include <math.h>

#define W_IMG 4096
// float(pi) - pi  (cos(pi_f) == -1 exactly, sin(pi_f) == -DPI)
#define DPI 8.742278e-8f
#define ZMIN 1e-12f

__device__ __forceinline__ float rcpa(float x){ float y; asm("rcp.approx.f32 %0, %1;" : "=f"(y) : "f"(x)); return y; }
__device__ __forceinline__ float rsqa(float x){ float y; asm("rsqrt.approx.f32 %0, %1;" : "=f"(y) : "f"(x)); return y; }
// y with sign flipped by sign(x): one LOP3
__device__ __forceinline__ float xsign(float y, float x){
    return __int_as_float(__float_as_int(y) ^ (__float_as_int(x) & 0x80000000u));
}

// ---------- robust (generic) sin/cos of atan(num/den): handles inf too ------
__device__ __forceinline__ void cs_atan_core(float num, float den, float& sa, float& ca) {
    float an = fabsf(num), ad = fabsf(den);
    bool sw = an > ad;
    float top = sw ? den : num;
    float bot = sw ? num : den;
    float q  = top * rcpa(bot);                 // |q| <= 1, or NaN
    float rr = rsqa(fmaf(q, q, 1.f));
    float sg = copysignf(1.f, num) * copysignf(1.f, den);
    ca = sw ? fabsf(q) * rr : rr;
    sa = sw ? sg * rr : q * rr;
}

// ---------- HOT finisher: requires nx_t, ny_t finite (guaranteed by z>ZMIN) --
__device__ __forceinline__ void hot_finish(
    float nx_t, float ny_t,
    const float* Xd, const float* Yd, const float* Zd,
    int sf, float& onx, float& ony, float& onz)
{
    float nt2 = fmaf(nx_t, nx_t, ny_t * ny_t);
    float r0  = rsqa(nt2);
    float ca  = fabsf(nx_t) * r0;           // cos(atan(ny/nx))
    float sa  = xsign(ny_t, nx_t) * r0;     // sin(atan(ny/nx))
    float a   = fmaf(sa, DPI, -ca);         // cos(atan + pi_f)
    float b   = -fmaf(ca, DPI, sa);         // sin(atan + pi_f)

    float rnz[4], nzv[4];
    int npos = 0, nneg = 0;
#pragma unroll
    for (int i = 0; i < 4; i++) {
        float nz_i = -fmaf(nx_t, Xd[i], ny_t * Yd[i]) * rcpa(Zd[i]);
        float rn = rsqa(fmaf(nz_i, nz_i, nt2));
        float v  = nz_i * rn;
        rnz[i] = (rn != rn) ? 0.f : rn;     // NaN rn -> all comps zero
        nzv[i] = (v  != v)  ? 0.f : v;
        npos += nzv[i] > 0.f;
        nneg += nzv[i] < 0.f;
    }

    float srn = 0.f, snz = 0.f;
    if (sf) {
        bool ps = npos >= nneg;
#pragma unroll
        for (int i = 0; i < 4; i++) {
            float fm = (ps ? (nzv[i] > 0.f) : (nzv[i] < 0.f)) ? 1.f : 0.f;
            srn = fmaf(fm, rnz[i], srn);
            snz = fmaf(fm, nzv[i], snz);
        }
    } else {
#pragma unroll
        for (int i = 0; i < 4; i++) { srn += rnz[i]; snz += nzv[i]; }
    }

    float snx = nx_t * srn, sny = ny_t * srn;
    float num = fmaf(snx, a, sny * b);
    float rr  = rsqa(fmaf(num, num, snz * snz));
    float st  = xsign(num, snz) * rr;       // sin(atan(num/snz))
    float ct  = fabsf(snz) * rr;            // cos(atan(num/snz))
    float nx = st * a, ny = st * b, nz = ct;
    if (nz != nz) { nx = 0.f; ny = 0.f; nz = -1.f; }
    float s = (ny > 0.f) ? -1.f : 1.f;
    onx = nx * s; ony = ny * s; onz = nz * s;
}

// ---------- generic finisher (robust to inf nx_t/ny_t) -----------------------
__device__ __forceinline__ void gen_finish(
    float nx_t, float ny_t,
    const float* Xd, const float* Yd, const float* Zd,
    int sf, float& onx, float& ony, float& onz)
{
    float sa, ca; cs_atan_core(ny_t, nx_t, sa, ca);
    float a = fmaf(sa, DPI, -ca);
    float b = -fmaf(ca, DPI, sa);
    float nt2 = fmaf(nx_t, nx_t, ny_t * ny_t);

    float nxv[4], nyv[4], nzv[4];
#pragma unroll
    for (int i = 0; i < 4; i++) {
        float nz_i = -fmaf(nx_t, Xd[i], ny_t * Yd[i]) * rcpa(Zd[i]);
        float rn = rsqa(fmaf(nz_i, nz_i, nt2));
        float vx = nx_t * rn, vy = ny_t * rn, vz = nz_i * rn;
        nxv[i] = (vx != vx) ? 0.f : vx;
        nyv[i] = (vy != vy) ? 0.f : vy;
        nzv[i] = (vz != vz) ? 0.f : vz;
    }
    if (sf) {
        int np = 0, nn = 0;
#pragma unroll
        for (int i = 0; i < 4; i++) { np += nzv[i] > 0.f; nn += nzv[i] < 0.f; }
        bool ps = np >= nn;
#pragma unroll
        for (int i = 0; i < 4; i++) {
            float fm = (ps ? (nzv[i] > 0.f) : (nzv[i] < 0.f)) ? 1.f : 0.f;
            nxv[i] *= fm; nyv[i] *= fm; nzv[i] *= fm;
        }
    }
    float snx = (nxv[0] + nxv[1]) + (nxv[2] + nxv[3]);
    float sny = (nyv[0] + nyv[1]) + (nyv[2] + nyv[3]);
    float snz = (nzv[0] + nzv[1]) + (nzv[2] + nzv[3]);

    float num = fmaf(snx, a, sny * b);
    float st, ct; cs_atan_core(num, snz, st, ct);
    float nx = st * a, ny = st * b, nz = ct;
    if (nz != nz) { nx = 0.f; ny = 0.f; nz = -1.f; }
    float s = (ny > 0.f) ? -1.f : 1.f;
    onx = nx * s; ony = ny * s; onz = nz * s;
}

__device__ __noinline__ void generic_pixel(const float* __restrict__ depth,
    int r, int c, int h, int w, float fx, float fy, float ifx,
    float cx, float cy, int sf, float& onx, float& ony, float& onz)
{
    const int dy[5] = {0, -1, 0, 0, 1};
    const int dx[5] = {0,  0,-1, 1, 0};
    float Xs[5], Ys[5], Zs[5], Ds[5];
#pragma unroll
    for (int i = 0; i < 5; i++) {
        int rr_ = r + dy[i], cc = c + dx[i];
        bool inb = (rr_ >= 0) & (rr_ < h) & (cc >= 0) & (cc < w);
        float X = 0.f, Y = 0.f, Z = 0.f, D = 0.f;
        if (inb) {
            float z = depth[rr_ * w + cc];
            Z = z;
            Y = z * ((float)rr_ - cy) * ifx;   // reference uses fx for Y too
            X = z * ((float)cc - cx) * ifx;
            if (Y <= 0.f) { Z = 0.f; Y = 0.f; } // X intentionally NOT zeroed
            if (Z != Z) Z = 0.f;
            D = rcpa(Z);                         // inf where Z == 0
        }
        Xs[i] = X; Ys[i] = Y; Zs[i] = Z; Ds[i] = D;
    }
    float nx_t = (Ds[3] - Ds[2]) * fx;
    float ny_t = (Ds[4] - Ds[1]) * fy;
    float Xd[4], Yd[4], Zd[4];
#pragma unroll
    for (int i = 0; i < 4; i++) {
        Xd[i] = Xs[0] - Xs[i + 1];
        Yd[i] = Ys[0] - Ys[i + 1];
        Zd[i] = Zs[0] - Zs[i + 1];
    }
    gen_finish(nx_t, ny_t, Xd, Yd, Zd, sf, onx, ony, onz);
}

__global__ __launch_bounds__(128)
void nim_kernel(const float* __restrict__ depth,
                const float* __restrict__ cam,
                const int*   __restrict__ sf_ptr,
                float* __restrict__ out,
                int h, int w)
{
    int r  = blockIdx.y * 4 + threadIdx.y;
    int c0 = (blockIdx.x * 32 + threadIdx.x) * 4;
    if (r >= h || c0 + 3 >= w) return;

    float fx = cam[0], fy = cam[4], cx = cam[2], cy = cam[5];
    float ifx = 1.0f / fx;
    int sf = sf_ptr[0];
    int hw = h * w;
    int base = r * w + c0;

    bool interior = (r >= 1) & (r < h - 1) & (c0 >= 4) & (c0 <= w - 8);

    if (interior) {
        float4 zu4 = *(const float4*)(depth + base - w);
        float4 zd4 = *(const float4*)(depth + base + w);
        float4 zm4 = *(const float4*)(depth + base);
        float  zml = depth[base - 1];
        float  zmr = depth[base + 4];

        float zu[4] = {zu4.x, zu4.y, zu4.z, zu4.w};
        float zd[4] = {zd4.x, zd4.y, zd4.z, zd4.w};
        float zm[6] = {zml, zm4.x, zm4.y, zm4.z, zm4.w, zmr};

        float fv0 = ((float)r       - cy) * ifx;
        float fvm = ((float)(r - 1) - cy) * ifx;
        float fvp = ((float)(r + 1) - cy) * ifx;

        // NaN-safe: all depths comfortably positive (keeps nx_t/ny_t finite,
        // nt2 un-overflowed in the hot finisher)
        bool allpos = (zu[0] > ZMIN) & (zu[1] > ZMIN) & (zu[2] > ZMIN) & (zu[3] > ZMIN)
                    & (zd[0] > ZMIN) & (zd[1] > ZMIN) & (zd[2] > ZMIN) & (zd[3] > ZMIN)
                    & (zm[0] > ZMIN) & (zm[1] > ZMIN) & (zm[2] > ZMIN)
                    & (zm[3] > ZMIN) & (zm[4] > ZMIN) & (zm[5] > ZMIN);

        if (allpos && fvp <= 0.f) {
            // Whole neighborhood masked (Y<=0 -> Z=0 -> D=inf) -> NaN cascade
            // -> reference emits exactly (0, 0, -1).
            float4 zro = make_float4(0.f, 0.f, 0.f, 0.f);
            float4 neg = make_float4(-1.f, -1.f, -1.f, -1.f);
            *(float4*)(out + base)          = zro;
            *(float4*)(out + base + hw)     = zro;
            *(float4*)(out + base + 2 * hw) = neg;
            return;
        }

        if (allpos && fvm > 0.f) {
            float Dm[6], Xm[6], Du[4], Dd[4];
#pragma unroll
            for (int j = 0; j < 6; j++) {
                float fu = ((float)(c0 - 1 + j) - cx) * ifx;
                Xm[j] = zm[j] * fu;
                Dm[j] = rcpa(zm[j]);
            }
#pragma unroll
            for (int p = 0; p < 4; p++) { Du[p] = rcpa(zu[p]); Dd[p] = rcpa(zd[p]); }

            float4 ox, oy, oz;
            float* oxp = &ox.x; float* oyp = &oy.x; float* ozp = &oz.x;
#pragma unroll
            for (int p = 0; p < 4; p++) {
                float zc  = zm[p + 1];
                float fuc = ((float)(c0 + p) - cx) * ifx;

                float nx_t = (Dm[p + 2] - Dm[p]) * fx;
                float ny_t = (Dd[p] - Du[p]) * fy;

                // neighbors: 0:up(-1,0) 1:left(0,-1) 2:right(0,1) 3:down(1,0)
                float Xd[4], Yd[4], Zd[4];
                Zd[0] = zc - zu[p];
                Xd[0] = Zd[0] * fuc;
                Yd[0] = fmaf(zc, fv0, -(zu[p] * fvm));
                Zd[1] = zc - zm[p];
                Xd[1] = Xm[p + 1] - Xm[p];
                Yd[1] = Zd[1] * fv0;
                Zd[2] = zc - zm[p + 2];
                Xd[2] = Xm[p + 1] - Xm[p + 2];
                Yd[2] = Zd[2] * fv0;
                Zd[3] = zc - zd[p];
                Xd[3] = Zd[3] * fuc;
                Yd[3] = fmaf(zc, fv0, -(zd[p] * fvp));

                hot_finish(nx_t, ny_t, Xd, Yd, Zd, sf, oxp[p], oyp[p], ozp[p]);
            }
            *(float4*)(out + base)          = ox;
            *(float4*)(out + base + hw)     = oy;
            *(float4*)(out + base + 2 * hw) = oz;
            return;
        }
    }

    // Borders, horizon band, pathological depth values.
    for (int p = 0; p < 4; p++) {
        float onx, ony, onz;
        generic_pixel(depth, r, c0 + p, h, w, fx, fy, ifx, cx, cy, sf, onx, ony, onz);
        out[base + p]          = onx;
        out[base + p + hw]     = ony;
        out[base + p + 2 * hw] = onz;
    }
}

extern "C" void kernel_launch(void* const* d_in, const int* in_sizes, int n_in,
                              void* d_out, int out_size) {
    const float* depth = (const float*)d_in[0];
    const float* cam   = (const float*)d_in[1];
    const int*   sf    = (const int*)d_in[2];
    float* out = (float*)d_out;

    int w = W_IMG;
    int h = in_sizes[0] / w;

    dim3 block(32, 4);
    dim3 grid((w + 127) / 128, (h + 3) / 4);
    nim_kernel<<<grid, block>>>(depth, cam, sf, out, h, w);
}